// round 9
// baseline (speedup 1.0000x reference)
#include <cuda_runtime.h>
#include <cuda_fp16.h>
#include <cstdint>

#define NTOK 4096
#define DDIM 512
#define NEXP 8
#define HDIM 1024
#define H2   2048

#define CH   64                  // K-chunk in halves = 128B rows
#define NCH1 (DDIM / CH)         // 8 chunks (fc1)
#define NCH2 (HDIM / CH)         // 16 chunks (fc2)
#define STAGE_BYTES 32768        // A tile 16KB + B tile 16KB
#define SMEM_DYN (3 * STAGE_BYTES + 2048)

// -------- scratch (device globals; no allocation allowed) --------
__device__ int    g_cnt[NEXP];
__device__ int    g_tok[NEXP * NTOK];
__device__ float  g_wt [NEXP * NTOK];
__device__ __half g_act[(size_t)NEXP * NTOK * HDIM];   // fp16 activations
__device__ __half g_xh [(size_t)NTOK * DDIM];          // fp16 x
__device__ __half g_w1h[(size_t)NEXP * H2 * DDIM];     // fp16 w1, rows interleaved: 2p=h1[p], 2p+1=h2[p]
__device__ __half g_w2h[(size_t)NEXP * DDIM * HDIM];   // fp16 w2

// ===================== helpers =====================
__device__ __forceinline__ uint32_t smem_u32(const void* p) {
    uint32_t a;
    asm("{ .reg .u64 t; cvta.to.shared.u64 t, %1; cvt.u32.u64 %0, t; }" : "=r"(a) : "l"(p));
    return a;
}
__device__ __forceinline__ uint32_t swz(uint32_t o) { return o ^ ((o >> 3) & 0x70); }

#define CP16(dst, src) asm volatile("cp.async.cg.shared.global [%0], [%1], 16;" :: "r"(dst), "l"(src) : "memory")
#define CPCOMMIT()     asm volatile("cp.async.commit_group;" ::: "memory")
#define CPWAIT1()      asm volatile("cp.async.wait_group 1;" ::: "memory")

__device__ __forceinline__ void ldsm4(uint32_t& r0, uint32_t& r1, uint32_t& r2, uint32_t& r3,
                                      uint32_t addr) {
    asm volatile("ldmatrix.sync.aligned.m8n8.x4.shared.b16 {%0,%1,%2,%3}, [%4];"
                 : "=r"(r0), "=r"(r1), "=r"(r2), "=r"(r3) : "r"(addr));
}
__device__ __forceinline__ void mma_f16(float* c, const uint32_t* a, uint32_t b0, uint32_t b1) {
    asm volatile(
        "mma.sync.aligned.m16n8k16.row.col.f32.f16.f16.f32 "
        "{%0,%1,%2,%3}, {%4,%5,%6,%7}, {%8,%9}, {%0,%1,%2,%3};"
        : "+f"(c[0]), "+f"(c[1]), "+f"(c[2]), "+f"(c[3])
        : "r"(a[0]), "r"(a[1]), "r"(a[2]), "r"(a[3]), "r"(b0), "r"(b1));
}
__device__ __forceinline__ uint4 pack8(const float* p) {
    float4 a = ((const float4*)p)[0], b = ((const float4*)p)[1];
    __half2 h0 = __floats2half2_rn(a.x, a.y), h1 = __floats2half2_rn(a.z, a.w);
    __half2 h2 = __floats2half2_rn(b.x, b.y), h3 = __floats2half2_rn(b.z, b.w);
    uint4 u;
    u.x = *(uint32_t*)&h0; u.y = *(uint32_t*)&h1;
    u.z = *(uint32_t*)&h2; u.w = *(uint32_t*)&h3;
    return u;
}

// GEMM over one K=64 chunk: 4 warps (2m x 2n), warp tile 64x64, acc[4][8][4] fp32.
__device__ __forceinline__ void gemm64(uint32_t Ab, uint32_t Bb, int wm, int wn,
                                       int lane, float acc[4][8][4]) {
    int lr = lane & 15;
    int hi = (lane >> 4) << 4;
#pragma unroll
    for (int ks = 0; ks < 4; ks++) {
        uint32_t afr[4][4];
#pragma unroll
        for (int mt = 0; mt < 4; mt++) {
            uint32_t off = (uint32_t)((wm + mt * 16 + lr) * 128 + ks * 32 + hi);
            ldsm4(afr[mt][0], afr[mt][1], afr[mt][2], afr[mt][3], Ab + swz(off));
        }
#pragma unroll
        for (int g = 0; g < 4; g++) {
            uint32_t b0, b1, b2, b3;
            uint32_t off = (uint32_t)((wn + g * 16 + lr) * 128 + ks * 32 + hi);
            ldsm4(b0, b1, b2, b3, Bb + swz(off));
#pragma unroll
            for (int mt = 0; mt < 4; mt++) {
                mma_f16(acc[mt][2 * g],     afr[mt], b0, b2);
                mma_f16(acc[mt][2 * g + 1], afr[mt], b1, b3);
            }
        }
    }
}

// issue one chunk with 128 threads: A 128 rows (thread -> row, 8x16B), B 128 rows (same)
__device__ __forceinline__ void issue_chunk(uint32_t Ab, uint32_t Bb,
                                            const __half* asrc, const __half* bsrc,
                                            uint32_t roff) {
#pragma unroll
    for (int s = 0; s < 8; s++) CP16(Ab + swz(roff + 16 * s), asrc + 8 * s);
#pragma unroll
    for (int s = 0; s < 8; s++) CP16(Bb + swz(roff + 16 * s), bsrc + 8 * s);
}

// =============================== pre: zero out + counters + fp16 converts ===============================
#define NX8  (NTOK * DDIM / 8)            // 262144
#define NW18 (NEXP * H2 * DDIM / 8)       // 1048576
#define NW28 (NEXP * DDIM * HDIM / 8)     // 524288
#define NZ4  (NTOK * DDIM / 4)            // 524288 float4 zeros
#define NPRE (NX8 + NW18 + NW28)
__global__ __launch_bounds__(256) void k_pre(const float* __restrict__ x,
                                             const float* __restrict__ w1,
                                             const float* __restrict__ w2,
                                             float* __restrict__ out) {
    int idx = blockIdx.x * blockDim.x + threadIdx.x;
    if (idx < NZ4) ((float4*)out)[idx] = make_float4(0.f, 0.f, 0.f, 0.f);
    if (idx < NEXP) g_cnt[idx] = 0;
    if (idx < NX8) {
        ((uint4*)g_xh)[idx] = pack8(x + idx * 8);
    } else if (idx < NX8 + NW18) {
        int i2 = idx - NX8;
        int o  = i2 * 8;
        int orow = o >> 9;
        int k    = o & 511;
        int e = orow >> 11;
        int r = orow & 2047;
        const float* src = w1 + ((size_t)(e << 11) + ((r & 1) << 10) + (r >> 1)) * DDIM + k;
        ((uint4*)g_w1h)[i2] = pack8(src);
    } else if (idx < NPRE) {
        int i3 = idx - NX8 - NW18;
        ((uint4*)g_w2h)[i3] = pack8(w2 + i3 * 8);
    }
}

// =============================== router (fp32 exact) ===============================
__global__ __launch_bounds__(256) void k_router(const float* __restrict__ x,
                                                const float* __restrict__ rw,
                                                const float* __restrict__ rb) {
    int tok  = blockIdx.x * 8 + (threadIdx.x >> 5);
    int lane = threadIdx.x & 31;
    if (tok >= NTOK) return;
    const float* xr = x + (size_t)tok * DDIM;
    float acc[NEXP];
#pragma unroll
    for (int e = 0; e < NEXP; e++) acc[e] = 0.f;
    for (int i = lane; i < DDIM; i += 32) {
        float xv = xr[i];
#pragma unroll
        for (int e = 0; e < NEXP; e++) acc[e] += xv * rw[e * DDIM + i];
    }
#pragma unroll
    for (int e = 0; e < NEXP; e++) {
#pragma unroll
        for (int o = 16; o > 0; o >>= 1)
            acc[e] += __shfl_xor_sync(0xffffffffu, acc[e], o);
    }
    if (lane == 0) {
        float lg[NEXP];
#pragma unroll
        for (int e = 0; e < NEXP; e++) lg[e] = acc[e] + rb[e];
        int i0 = 0; float v0 = lg[0];
#pragma unroll
        for (int e = 1; e < NEXP; e++) if (lg[e] > v0) { v0 = lg[e]; i0 = e; }
        int i1 = -1; float v1 = -3.0e38f;
#pragma unroll
        for (int e = 0; e < NEXP; e++) if (e != i0 && lg[e] > v1) { v1 = lg[e]; i1 = e; }
        float t  = __expf(v1 - v0);
        float w0 = 1.f / (1.f + t);
        float w1_ = 1.f - w0;
        int s0 = atomicAdd(&g_cnt[i0], 1);
        g_tok[i0 * NTOK + s0] = tok;  g_wt[i0 * NTOK + s0] = w0;
        int s1 = atomicAdd(&g_cnt[i1], 1);
        g_tok[i1 * NTOK + s1] = tok;  g_wt[i1 * NTOK + s1] = w1_;
    }
}

// =============================== fc1: async fp16 mma + SwiGLU ===============================
// Block tile: 128 tokens x 128 interleaved cols (64 pairs). grid=(HDIM/64, NTOK/128, NEXP).
// 4 warps (2m x 2n), warp tile 64x64, 128 threads, 2 CTAs/SM.
__global__ __launch_bounds__(128, 2) void k_fc1(const float* __restrict__ b1) {
    int e   = blockIdx.z;
    int cnt = g_cnt[e];
    int m0  = blockIdx.y * 128;
    if (m0 >= cnt) return;
    int c0  = blockIdx.x * 64;   // pair base

    extern __shared__ char smem[];
    uint32_t sb    = smem_u32(smem);
    uint32_t tiles = (sb + 1023) & ~1023u;
    int* s_tok = (int*)(smem + (tiles - sb) + 3 * STAGE_BYTES);

    int tid = threadIdx.x, wid = tid >> 5, lane = tid & 31;
    {
        int m = m0 + tid;
        s_tok[tid] = (m < cnt) ? g_tok[e * NTOK + m] : 0;
    }
    __syncthreads();

    uint32_t roff = (uint32_t)(tid * 128);
    const __half* asrc = g_xh + (size_t)s_tok[tid] * DDIM;
    const __half* bsrc = g_w1h + ((size_t)e * H2 + 2 * c0 + tid) * DDIM;

    int wm = (wid >> 1) * 64;
    int wn = (wid & 1) * 64;
    float acc[4][8][4] = {};

#pragma unroll
    for (int c = 0; c < 2; c++) {
        uint32_t Ab = tiles + c * STAGE_BYTES, Bb = Ab + 16384;
        issue_chunk(Ab, Bb, asrc + c * CH, bsrc + c * CH, roff);
        CPCOMMIT();
    }

    for (int c = 0; c < NCH1; c++) {
        CPWAIT1();
        __syncthreads();
        if (c + 2 < NCH1) {
            int s2 = (c + 2) % 3;
            issue_chunk(tiles + s2 * STAGE_BYTES, tiles + s2 * STAGE_BYTES + 16384,
                        asrc + (c + 2) * CH, bsrc + (c + 2) * CH, roff);
        }
        CPCOMMIT();
        int s = c % 3;
        gemm64(tiles + s * STAGE_BYTES, tiles + s * STAGE_BYTES + 16384, wm, wn, lane, acc);
        __syncthreads();
    }

    // epilogue: acc col pairs (even,odd) = (h1,h2); write fp16 activations
    const float* bb = b1 + (size_t)e * H2;
#pragma unroll
    for (int mt = 0; mt < 4; mt++) {
        int r_lo = m0 + wm + mt * 16 + (lane >> 2);
#pragma unroll
        for (int nt = 0; nt < 8; nt++) {
            int p = (wn >> 1) + nt * 4 + (lane & 3);
            int hcol = c0 + p;
            float bh1 = bb[hcol];
            float bh2 = bb[HDIM + hcol];
            if (r_lo < cnt) {
                float h1 = acc[mt][nt][0] + bh1;
                float h2 = acc[mt][nt][1] + bh2;
                g_act[((size_t)e * NTOK + r_lo) * HDIM + hcol] =
                    __float2half_rn((h1 / (1.f + __expf(-h1))) * h2);
            }
            int r_hi = r_lo + 8;
            if (r_hi < cnt) {
                float h1 = acc[mt][nt][2] + bh1;
                float h2 = acc[mt][nt][3] + bh2;
                g_act[((size_t)e * NTOK + r_hi) * HDIM + hcol] =
                    __float2half_rn((h1 / (1.f + __expf(-h1))) * h2);
            }
        }
    }
}

// =============================== fc2: async fp16 mma + weighted combine ===============================
// Block tile: 128 tokens x 128 d-outputs. grid=(DDIM/128, NTOK/128, NEXP).
__global__ __launch_bounds__(128, 2) void k_fc2(const float* __restrict__ b2,
                                                float* __restrict__ out) {
    int e   = blockIdx.z;
    int cnt = g_cnt[e];
    int m0  = blockIdx.y * 128;
    if (m0 >= cnt) return;
    int n0  = blockIdx.x * 128;

    extern __shared__ char smem[];
    uint32_t sb    = smem_u32(smem);
    uint32_t tiles = (sb + 1023) & ~1023u;
    int*   s_tok = (int*)(smem + (tiles - sb) + 3 * STAGE_BYTES);
    float* s_wt  = (float*)(smem + (tiles - sb) + 3 * STAGE_BYTES + 512);

    int tid = threadIdx.x, wid = tid >> 5, lane = tid & 31;
    {
        int m = m0 + tid;
        if (m < cnt) { s_tok[tid] = g_tok[e * NTOK + m]; s_wt[tid] = g_wt[e * NTOK + m]; }
        else         { s_tok[tid] = 0;                   s_wt[tid] = 0.f; }
    }
    __syncthreads();

    uint32_t roff = (uint32_t)(tid * 128);
    const __half* asrc = g_act + ((size_t)e * NTOK + m0 + tid) * HDIM;
    const __half* bsrc = g_w2h + ((size_t)e * DDIM + n0 + tid) * HDIM;

    int wm = (wid >> 1) * 64;
    int wn = (wid & 1) * 64;
    float acc[4][8][4] = {};

#pragma unroll
    for (int c = 0; c < 2; c++) {
        uint32_t Ab = tiles + c * STAGE_BYTES, Bb = Ab + 16384;
        issue_chunk(Ab, Bb, asrc + c * CH, bsrc + c * CH, roff);
        CPCOMMIT();
    }

    for (int c = 0; c < NCH2; c++) {
        CPWAIT1();
        __syncthreads();
        if (c + 2 < NCH2) {
            int s2 = (c + 2) % 3;
            issue_chunk(tiles + s2 * STAGE_BYTES, tiles + s2 * STAGE_BYTES + 16384,
                        asrc + (c + 2) * CH, bsrc + (c + 2) * CH, roff);
        }
        CPCOMMIT();
        int s = c % 3;
        gemm64(tiles + s * STAGE_BYTES, tiles + s * STAGE_BYTES + 16384, wm, wn, lane, acc);
        __syncthreads();
    }

    const float* bb = b2 + (size_t)e * DDIM;
#pragma unroll
    for (int mt = 0; mt < 4; mt++) {
        int r_lo = wm + mt * 16 + (lane >> 2);
#pragma unroll
        for (int nt = 0; nt < 8; nt++) {
            int n_e = n0 + wn + nt * 8 + 2 * (lane & 3);
            float be = bb[n_e];
            float bo = bb[n_e + 1];
            if (m0 + r_lo < cnt) {
                int tok = s_tok[r_lo]; float wt = s_wt[r_lo];
                atomicAdd(&out[(size_t)tok * DDIM + n_e],     (acc[mt][nt][0] + be) * wt);
                atomicAdd(&out[(size_t)tok * DDIM + n_e + 1], (acc[mt][nt][1] + bo) * wt);
            }
            int r_hi = r_lo + 8;
            if (m0 + r_hi < cnt) {
                int tok = s_tok[r_hi]; float wt = s_wt[r_hi];
                atomicAdd(&out[(size_t)tok * DDIM + n_e],     (acc[mt][nt][2] + be) * wt);
                atomicAdd(&out[(size_t)tok * DDIM + n_e + 1], (acc[mt][nt][3] + bo) * wt);
            }
        }
    }
}

// =============================== launch ===============================
extern "C" void kernel_launch(void* const* d_in, const int* in_sizes, int n_in,
                              void* d_out, int out_size) {
    const float* x   = (const float*)d_in[0];
    const float* rw  = (const float*)d_in[1];
    const float* rb  = (const float*)d_in[2];
    const float* f1w = (const float*)d_in[3];
    const float* f1b = (const float*)d_in[4];
    const float* f2w = (const float*)d_in[5];
    const float* f2b = (const float*)d_in[6];
    float* out = (float*)d_out;

    cudaFuncSetAttribute(k_fc1, cudaFuncAttributeMaxDynamicSharedMemorySize, SMEM_DYN);
    cudaFuncSetAttribute(k_fc2, cudaFuncAttributeMaxDynamicSharedMemorySize, SMEM_DYN);

    k_pre<<<(NPRE + 255) / 256, 256>>>(x, f1w, f2w, out);
    k_router<<<NTOK / 8, 256>>>(x, rw, rb);
    k_fc1<<<dim3(HDIM / 64, NTOK / 128, NEXP), 128, SMEM_DYN>>>(f1b);
    k_fc2<<<dim3(DDIM / 128, NTOK / 128, NEXP), 128, SMEM_DYN>>>(f2b, out);
}

// round 13
// speedup vs baseline: 1.3708x; 1.3708x over previous
#include <cuda_runtime.h>
#include <cuda_fp16.h>
#include <cstdint>

#define NTOK 4096
#define DDIM 512
#define NEXP 8
#define HDIM 1024
#define H2   2048

#define CH   64                  // K-chunk in halves = 128B rows
#define NCH1 (DDIM / CH)         // 8 chunks (fc1)
#define NCH2 (HDIM / CH)         // 16 chunks (fc2)
#define STAGE_BYTES 32768        // A tile 16KB + B tile 16KB
#define SMEM_DYN (3 * STAGE_BYTES + 2048)

// -------- scratch (device globals; no allocation allowed) --------
__device__ int    g_cnt[NEXP];
__device__ int    g_tok[NEXP * NTOK];
__device__ float  g_wt [NEXP * NTOK];
__device__ int2   g_slot[NTOK];                        // token -> (e0*NTOK+s0, e1*NTOK+s1)
__device__ float2 g_wp [NTOK];                         // token -> (w0, w1)
__device__ __half g_act[(size_t)NEXP * NTOK * HDIM];   // fp16 activations
__device__ float  g_y  [(size_t)NEXP * NTOK * DDIM];   // fp32 per-slot fc2 output (+bias)
__device__ __half g_xh [(size_t)NTOK * DDIM];          // fp16 x
__device__ __half g_w1h[(size_t)NEXP * H2 * DDIM];     // fp16 w1, rows interleaved: 2p=h1[p], 2p+1=h2[p]
__device__ __half g_w2h[(size_t)NEXP * DDIM * HDIM];   // fp16 w2

// ===================== helpers =====================
__device__ __forceinline__ uint32_t smem_u32(const void* p) {
    uint32_t a;
    asm("{ .reg .u64 t; cvta.to.shared.u64 t, %1; cvt.u32.u64 %0, t; }" : "=r"(a) : "l"(p));
    return a;
}
__device__ __forceinline__ uint32_t swz(uint32_t o) { return o ^ ((o >> 3) & 0x70); }

#define CP16(dst, src) asm volatile("cp.async.cg.shared.global [%0], [%1], 16;" :: "r"(dst), "l"(src) : "memory")
#define CPCOMMIT()     asm volatile("cp.async.commit_group;" ::: "memory")
#define CPWAIT1()      asm volatile("cp.async.wait_group 1;" ::: "memory")

__device__ __forceinline__ void ldsm4(uint32_t& r0, uint32_t& r1, uint32_t& r2, uint32_t& r3,
                                      uint32_t addr) {
    asm volatile("ldmatrix.sync.aligned.m8n8.x4.shared.b16 {%0,%1,%2,%3}, [%4];"
                 : "=r"(r0), "=r"(r1), "=r"(r2), "=r"(r3) : "r"(addr));
}
__device__ __forceinline__ void mma_f16(float* c, const uint32_t* a, uint32_t b0, uint32_t b1) {
    asm volatile(
        "mma.sync.aligned.m16n8k16.row.col.f32.f16.f16.f32 "
        "{%0,%1,%2,%3}, {%4,%5,%6,%7}, {%8,%9}, {%0,%1,%2,%3};"
        : "+f"(c[0]), "+f"(c[1]), "+f"(c[2]), "+f"(c[3])
        : "r"(a[0]), "r"(a[1]), "r"(a[2]), "r"(a[3]), "r"(b0), "r"(b1));
}
__device__ __forceinline__ uint4 pack8(const float* p) {
    float4 a = ((const float4*)p)[0], b = ((const float4*)p)[1];
    __half2 h0 = __floats2half2_rn(a.x, a.y), h1 = __floats2half2_rn(a.z, a.w);
    __half2 h2 = __floats2half2_rn(b.x, b.y), h3 = __floats2half2_rn(b.z, b.w);
    uint4 u;
    u.x = *(uint32_t*)&h0; u.y = *(uint32_t*)&h1;
    u.z = *(uint32_t*)&h2; u.w = *(uint32_t*)&h3;
    return u;
}

// GEMM over one K=64 chunk: 8 warps (4m x 2n), warp tile 32x64, acc[2][8][4] fp32.
__device__ __forceinline__ void gemm64(uint32_t Ab, uint32_t Bb, int wm, int wn,
                                       int lane, float acc[2][8][4]) {
    int lr = lane & 15;
    int hi = (lane >> 4) << 4;
#pragma unroll
    for (int ks = 0; ks < 4; ks++) {
        uint32_t afr[2][4];
#pragma unroll
        for (int mt = 0; mt < 2; mt++) {
            uint32_t off = (uint32_t)((wm + mt * 16 + lr) * 128 + ks * 32 + hi);
            ldsm4(afr[mt][0], afr[mt][1], afr[mt][2], afr[mt][3], Ab + swz(off));
        }
#pragma unroll
        for (int g = 0; g < 4; g++) {
            uint32_t b0, b1, b2, b3;
            uint32_t off = (uint32_t)((wn + g * 16 + lr) * 128 + ks * 32 + hi);
            ldsm4(b0, b1, b2, b3, Bb + swz(off));
            mma_f16(acc[0][2 * g],     afr[0], b0, b2);
            mma_f16(acc[1][2 * g],     afr[1], b0, b2);
            mma_f16(acc[0][2 * g + 1], afr[0], b1, b3);
            mma_f16(acc[1][2 * g + 1], afr[1], b1, b3);
        }
    }
}

// issue one chunk's A+B tiles with 256 threads: each thread 4x16B of A and 4x16B of B
__device__ __forceinline__ void issue_chunk(uint32_t Ab, uint32_t Bb,
                                            const __half* asrc, const __half* bsrc,
                                            uint32_t dstoff) {
#pragma unroll
    for (int s = 0; s < 4; s++) {
        CP16(Ab + swz(dstoff + 16 * s), asrc + 8 * s);
        CP16(Bb + swz(dstoff + 16 * s), bsrc + 8 * s);
    }
}

// =============================== pre: counters + fp16 converts ===============================
#define NX8  (NTOK * DDIM / 8)            // 262144
#define NW18 (NEXP * H2 * DDIM / 8)       // 1048576
#define NW28 (NEXP * DDIM * HDIM / 8)     // 524288
#define NPRE (NX8 + NW18 + NW28)
__global__ __launch_bounds__(256) void k_pre(const float* __restrict__ x,
                                             const float* __restrict__ w1,
                                             const float* __restrict__ w2) {
    int idx = blockIdx.x * blockDim.x + threadIdx.x;
    if (idx < NEXP) g_cnt[idx] = 0;
    if (idx < NX8) {
        ((uint4*)g_xh)[idx] = pack8(x + idx * 8);
    } else if (idx < NX8 + NW18) {
        int i2 = idx - NX8;
        int o  = i2 * 8;
        int orow = o >> 9;
        int k    = o & 511;
        int e = orow >> 11;
        int r = orow & 2047;
        const float* src = w1 + ((size_t)(e << 11) + ((r & 1) << 10) + (r >> 1)) * DDIM + k;
        ((uint4*)g_w1h)[i2] = pack8(src);
    } else if (idx < NPRE) {
        int i3 = idx - NX8 - NW18;
        ((uint4*)g_w2h)[i3] = pack8(w2 + i3 * 8);
    }
}

// =============================== router (fp32 exact) ===============================
__global__ __launch_bounds__(256) void k_router(const float* __restrict__ x,
                                                const float* __restrict__ rw,
                                                const float* __restrict__ rb) {
    int tok  = blockIdx.x * 8 + (threadIdx.x >> 5);
    int lane = threadIdx.x & 31;
    if (tok >= NTOK) return;
    const float* xr = x + (size_t)tok * DDIM;
    float acc[NEXP];
#pragma unroll
    for (int e = 0; e < NEXP; e++) acc[e] = 0.f;
    for (int i = lane; i < DDIM; i += 32) {
        float xv = xr[i];
#pragma unroll
        for (int e = 0; e < NEXP; e++) acc[e] += xv * rw[e * DDIM + i];
    }
#pragma unroll
    for (int e = 0; e < NEXP; e++) {
#pragma unroll
        for (int o = 16; o > 0; o >>= 1)
            acc[e] += __shfl_xor_sync(0xffffffffu, acc[e], o);
    }
    if (lane == 0) {
        float lg[NEXP];
#pragma unroll
        for (int e = 0; e < NEXP; e++) lg[e] = acc[e] + rb[e];
        int i0 = 0; float v0 = lg[0];
#pragma unroll
        for (int e = 1; e < NEXP; e++) if (lg[e] > v0) { v0 = lg[e]; i0 = e; }
        int i1 = -1; float v1 = -3.0e38f;
#pragma unroll
        for (int e = 0; e < NEXP; e++) if (e != i0 && lg[e] > v1) { v1 = lg[e]; i1 = e; }
        float t  = __expf(v1 - v0);
        float w0 = 1.f / (1.f + t);
        float w1_ = 1.f - w0;
        int s0 = atomicAdd(&g_cnt[i0], 1);
        g_tok[i0 * NTOK + s0] = tok;
        int s1 = atomicAdd(&g_cnt[i1], 1);
        g_tok[i1 * NTOK + s1] = tok;
        g_slot[tok] = make_int2(i0 * NTOK + s0, i1 * NTOK + s1);
        g_wp[tok]   = make_float2(w0, w1_);
    }
}

// =============================== fc1: async fp16 mma + SwiGLU ===============================
// Block tile: 128 tokens x 128 interleaved cols (64 pairs). grid=(HDIM/64, NTOK/128, NEXP).
// 8 warps (4m x 2n), warp tile 32x64, 256 threads, 2 CTAs/SM.
__global__ __launch_bounds__(256, 2) void k_fc1(const float* __restrict__ b1) {
    int e   = blockIdx.z;
    int cnt = g_cnt[e];
    int m0  = blockIdx.y * 128;
    if (m0 >= cnt) return;
    int c0  = blockIdx.x * 64;   // pair base

    extern __shared__ char smem[];
    uint32_t sb    = smem_u32(smem);
    uint32_t tiles = (sb + 1023) & ~1023u;
    int* s_tok = (int*)(smem + (tiles - sb) + 3 * STAGE_BYTES);

    int tid = threadIdx.x, wid = tid >> 5, lane = tid & 31;
    if (tid < 128) {
        int m = m0 + tid;
        s_tok[tid] = (m < cnt) ? g_tok[e * NTOK + m] : 0;
    }
    __syncthreads();

    uint32_t dstoff = (uint32_t)((tid >> 1) * 128 + (tid & 1) * 64);
    const __half* asrc = g_xh + (size_t)s_tok[tid >> 1] * DDIM + (tid & 1) * 32;
    const __half* bsrc = g_w1h + ((size_t)e * H2 + 2 * c0 + (tid >> 1)) * DDIM + (tid & 1) * 32;

    int wm = (wid >> 1) * 32;
    int wn = (wid & 1) * 64;
    float acc[2][8][4] = {};

#pragma unroll
    for (int c = 0; c < 2; c++) {
        uint32_t Ab = tiles + c * STAGE_BYTES, Bb = Ab + 16384;
        issue_chunk(Ab, Bb, asrc + c * CH, bsrc + c * CH, dstoff);
        CPCOMMIT();
    }

    for (int c = 0; c < NCH1; c++) {
        CPWAIT1();
        __syncthreads();
        if (c + 2 < NCH1) {
            int s2 = (c + 2) % 3;
            issue_chunk(tiles + s2 * STAGE_BYTES, tiles + s2 * STAGE_BYTES + 16384,
                        asrc + (c + 2) * CH, bsrc + (c + 2) * CH, dstoff);
        }
        CPCOMMIT();
        int s = c % 3;
        gemm64(tiles + s * STAGE_BYTES, tiles + s * STAGE_BYTES + 16384, wm, wn, lane, acc);
    }

    // epilogue: acc col pairs (even,odd) = (h1,h2); write fp16 activations
    const float* bb = b1 + (size_t)e * H2;
#pragma unroll
    for (int mt = 0; mt < 2; mt++) {
        int r_lo = m0 + wm + mt * 16 + (lane >> 2);
#pragma unroll
        for (int nt = 0; nt < 8; nt++) {
            int p = (wn >> 1) + nt * 4 + (lane & 3);
            int hcol = c0 + p;
            float bh1 = bb[hcol];
            float bh2 = bb[HDIM + hcol];
            if (r_lo < cnt) {
                float h1 = acc[mt][nt][0] + bh1;
                float h2 = acc[mt][nt][1] + bh2;
                g_act[((size_t)e * NTOK + r_lo) * HDIM + hcol] =
                    __float2half_rn((h1 / (1.f + __expf(-h1))) * h2);
            }
            int r_hi = r_lo + 8;
            if (r_hi < cnt) {
                float h1 = acc[mt][nt][2] + bh1;
                float h2 = acc[mt][nt][3] + bh2;
                g_act[((size_t)e * NTOK + r_hi) * HDIM + hcol] =
                    __float2half_rn((h1 / (1.f + __expf(-h1))) * h2);
            }
        }
    }
}

// =============================== fc2: async fp16 mma, slot output (no atomics) ===============================
// Block tile: 128 tokens x 128 d-outputs. grid=(DDIM/128, NTOK/128, NEXP).
__global__ __launch_bounds__(256, 2) void k_fc2(const float* __restrict__ b2) {
    int e   = blockIdx.z;
    int cnt = g_cnt[e];
    int m0  = blockIdx.y * 128;
    if (m0 >= cnt) return;
    int n0  = blockIdx.x * 128;

    extern __shared__ char smem[];
    uint32_t sb    = smem_u32(smem);
    uint32_t tiles = (sb + 1023) & ~1023u;

    int tid = threadIdx.x, wid = tid >> 5, lane = tid & 31;

    uint32_t dstoff = (uint32_t)((tid >> 1) * 128 + (tid & 1) * 64);
    const __half* asrc = g_act + ((size_t)e * NTOK + m0 + (tid >> 1)) * HDIM + (tid & 1) * 32;
    const __half* bsrc = g_w2h + ((size_t)e * DDIM + n0 + (tid >> 1)) * HDIM + (tid & 1) * 32;

    int wm = (wid >> 1) * 32;
    int wn = (wid & 1) * 64;
    float acc[2][8][4] = {};

#pragma unroll
    for (int c = 0; c < 2; c++) {
        uint32_t Ab = tiles + c * STAGE_BYTES, Bb = Ab + 16384;
        issue_chunk(Ab, Bb, asrc + c * CH, bsrc + c * CH, dstoff);
        CPCOMMIT();
    }

    for (int c = 0; c < NCH2; c++) {
        CPWAIT1();
        __syncthreads();
        if (c + 2 < NCH2) {
            int s2 = (c + 2) % 3;
            issue_chunk(tiles + s2 * STAGE_BYTES, tiles + s2 * STAGE_BYTES + 16384,
                        asrc + (c + 2) * CH, bsrc + (c + 2) * CH, dstoff);
        }
        CPCOMMIT();
        int s = c % 3;
        gemm64(tiles + s * STAGE_BYTES, tiles + s * STAGE_BYTES + 16384, wm, wn, lane, acc);
    }

    // epilogue: y + bias -> g_y[slot] (plain float2 stores, fully parallel)
    const float* bb = b2 + (size_t)e * DDIM;
    float* ybase = g_y + ((size_t)e * NTOK + m0) * DDIM;
#pragma unroll
    for (int mt = 0; mt < 2; mt++) {
        int r_lo = wm + mt * 16 + (lane >> 2);
#pragma unroll
        for (int nt = 0; nt < 8; nt++) {
            int n_e = n0 + wn + nt * 8 + 2 * (lane & 3);
            float be = bb[n_e];
            float bo = bb[n_e + 1];
            if (m0 + r_lo < cnt)
                *(float2*)(ybase + (size_t)r_lo * DDIM + n_e) =
                    make_float2(acc[mt][nt][0] + be, acc[mt][nt][1] + bo);
            int r_hi = r_lo + 8;
            if (m0 + r_hi < cnt)
                *(float2*)(ybase + (size_t)r_hi * DDIM + n_e) =
                    make_float2(acc[mt][nt][2] + be, acc[mt][nt][3] + bo);
        }
    }
}

// =============================== combine: out = w0*y[slot0] + w1*y[slot1] ===============================
// one warp per token; 512 floats = 4 float4 per lane. grid = NTOK/8 blocks of 256.
__global__ __launch_bounds__(256) void k_comb(float* __restrict__ out) {
    int tok  = blockIdx.x * 8 + (threadIdx.x >> 5);
    int lane = threadIdx.x & 31;
    int2   sl = g_slot[tok];
    float2 w  = g_wp[tok];
    const float* y0 = g_y + (size_t)sl.x * DDIM;
    const float* y1 = g_y + (size_t)sl.y * DDIM;
    float* op = out + (size_t)tok * DDIM;
#pragma unroll
    for (int i = 0; i < 4; i++) {
        int j = (i * 32 + lane) * 4;
        float4 a = *(const float4*)(y0 + j);
        float4 b = *(const float4*)(y1 + j);
        float4 r;
        r.x = w.x * a.x + w.y * b.x;
        r.y = w.x * a.y + w.y * b.y;
        r.z = w.x * a.z + w.y * b.z;
        r.w = w.x * a.w + w.y * b.w;
        *(float4*)(op + j) = r;
    }
}

// =============================== launch ===============================
extern "C" void kernel_launch(void* const* d_in, const int* in_sizes, int n_in,
                              void* d_out, int out_size) {
    const float* x   = (const float*)d_in[0];
    const float* rw  = (const float*)d_in[1];
    const float* rb  = (const float*)d_in[2];
    const float* f1w = (const float*)d_in[3];
    const float* f1b = (const float*)d_in[4];
    const float* f2w = (const float*)d_in[5];
    const float* f2b = (const float*)d_in[6];
    float* out = (float*)d_out;

    cudaFuncSetAttribute(k_fc1, cudaFuncAttributeMaxDynamicSharedMemorySize, SMEM_DYN);
    cudaFuncSetAttribute(k_fc2, cudaFuncAttributeMaxDynamicSharedMemorySize, SMEM_DYN);

    k_pre<<<(NPRE + 255) / 256, 256>>>(x, f1w, f2w);
    k_router<<<NTOK / 8, 256>>>(x, rw, rb);
    k_fc1<<<dim3(HDIM / 64, NTOK / 128, NEXP), 256, SMEM_DYN>>>(f1b);
    k_fc2<<<dim3(DDIM / 128, NTOK / 128, NEXP), 256, SMEM_DYN>>>(f2b);
    k_comb<<<NTOK / 8, 256>>>(out);
}

// round 15
// speedup vs baseline: 1.4759x; 1.0767x over previous
#include <cuda_runtime.h>
#include <cuda_fp16.h>
#include <cstdint>

#define NTOK 4096
#define DDIM 512
#define NEXP 8
#define HDIM 1024
#define H2   2048

#define CH   64                  // K-chunk in halves = 128B rows
#define NCH1 (DDIM / CH)         // 8 chunks (fc1)
#define NCH2 (HDIM / CH)         // 16 chunks (fc2)
#define STAGE_BYTES 32768        // A tile 16KB + B tile 16KB
#define SMEM_DYN (3 * STAGE_BYTES + 2048)

// -------- scratch (device globals; no allocation allowed) --------
__device__ int    g_cnt[NEXP];
__device__ int    g_tok[NEXP * NTOK];
__device__ int2   g_slot[NTOK];                        // token -> (e0*NTOK+s0, e1*NTOK+s1)
__device__ float2 g_wp [NTOK];                         // token -> (w0, w1)
__device__ __half g_act[(size_t)NEXP * NTOK * HDIM];   // fp16 activations
__device__ float  g_y  [(size_t)NEXP * NTOK * DDIM];   // fp32 per-slot fc2 output (+bias)
__device__ __half g_xh [(size_t)NTOK * DDIM];          // fp16 x
__device__ __half g_w1h[(size_t)NEXP * H2 * DDIM];     // fp16 w1, rows interleaved: 2p=h1[p], 2p+1=h2[p]
__device__ __half g_w2h[(size_t)NEXP * DDIM * HDIM];   // fp16 w2

// ===================== helpers =====================
__device__ __forceinline__ uint32_t smem_u32(const void* p) {
    uint32_t a;
    asm("{ .reg .u64 t; cvta.to.shared.u64 t, %1; cvt.u32.u64 %0, t; }" : "=r"(a) : "l"(p));
    return a;
}
__device__ __forceinline__ uint32_t swz(uint32_t o) { return o ^ ((o >> 3) & 0x70); }

#define CP16(dst, src)  asm volatile("cp.async.cg.shared.global [%0], [%1], 16;" :: "r"(dst), "l"(src) : "memory")
// .noinc: copy-completion counts as a TRUE arrival against the init count
// (default form pre-increments expected count -> base 256 never satisfied -> R10 deadlock)
#define CP_ARRIVE(mb)   asm volatile("cp.async.mbarrier.arrive.noinc.shared.b64 [%0];" :: "r"(mb) : "memory")
#define MBAR_INIT(mb, cnt) asm volatile("mbarrier.init.shared.b64 [%0], %1;" :: "r"(mb), "r"(cnt) : "memory")
#define MBAR_ARRIVE(mb) asm volatile("mbarrier.arrive.shared.b64 _, [%0];" :: "r"(mb) : "memory")

__device__ __forceinline__ void mbar_wait(uint32_t mb, int parity) {
    uint32_t done;
    asm volatile(
        "{ .reg .pred p;"
        " mbarrier.try_wait.parity.acquire.cta.shared::cta.b64 p, [%1], %2;"
        " selp.b32 %0, 1, 0, p; }"
        : "=r"(done) : "r"(mb), "r"(parity) : "memory");
    if (!done) {
        asm volatile(
            "{ .reg .pred P1;"
            "W_%=: mbarrier.try_wait.parity.acquire.cta.shared::cta.b64 P1, [%0], %1, 0x989680;"
            " @P1 bra.uni D_%=;"
            " bra.uni W_%=;"
            "D_%=: }"
            :: "r"(mb), "r"(parity) : "memory");
    }
}

__device__ __forceinline__ void ldsm4(uint32_t& r0, uint32_t& r1, uint32_t& r2, uint32_t& r3,
                                      uint32_t addr) {
    asm volatile("ldmatrix.sync.aligned.m8n8.x4.shared.b16 {%0,%1,%2,%3}, [%4];"
                 : "=r"(r0), "=r"(r1), "=r"(r2), "=r"(r3) : "r"(addr));
}
__device__ __forceinline__ void mma_f16(float* c, const uint32_t* a, uint32_t b0, uint32_t b1) {
    asm volatile(
        "mma.sync.aligned.m16n8k16.row.col.f32.f16.f16.f32 "
        "{%0,%1,%2,%3}, {%4,%5,%6,%7}, {%8,%9}, {%0,%1,%2,%3};"
        : "+f"(c[0]), "+f"(c[1]), "+f"(c[2]), "+f"(c[3])
        : "r"(a[0]), "r"(a[1]), "r"(a[2]), "r"(a[3]), "r"(b0), "r"(b1));
}
__device__ __forceinline__ uint4 pack8(const float* p) {
    float4 a = ((const float4*)p)[0], b = ((const float4*)p)[1];
    __half2 h0 = __floats2half2_rn(a.x, a.y), h1 = __floats2half2_rn(a.z, a.w);
    __half2 h2 = __floats2half2_rn(b.x, b.y), h3 = __floats2half2_rn(b.z, b.w);
    uint4 u;
    u.x = *(uint32_t*)&h0; u.y = *(uint32_t*)&h1;
    u.z = *(uint32_t*)&h2; u.w = *(uint32_t*)&h3;
    return u;
}

// GEMM over one K=64 chunk: 8 warps (4m x 2n), warp tile 32x64, acc[2][8][4] fp32.
__device__ __forceinline__ void gemm64(uint32_t Ab, uint32_t Bb, int wm, int wn,
                                       int lane, float acc[2][8][4]) {
    int lr = lane & 15;
    int hi = (lane >> 4) << 4;
#pragma unroll
    for (int ks = 0; ks < 4; ks++) {
        uint32_t afr[2][4];
#pragma unroll
        for (int mt = 0; mt < 2; mt++) {
            uint32_t off = (uint32_t)((wm + mt * 16 + lr) * 128 + ks * 32 + hi);
            ldsm4(afr[mt][0], afr[mt][1], afr[mt][2], afr[mt][3], Ab + swz(off));
        }
#pragma unroll
        for (int g = 0; g < 4; g++) {
            uint32_t b0, b1, b2, b3;
            uint32_t off = (uint32_t)((wn + g * 16 + lr) * 128 + ks * 32 + hi);
            ldsm4(b0, b1, b2, b3, Bb + swz(off));
            mma_f16(acc[0][2 * g],     afr[0], b0, b2);
            mma_f16(acc[1][2 * g],     afr[1], b0, b2);
            mma_f16(acc[0][2 * g + 1], afr[0], b1, b3);
            mma_f16(acc[1][2 * g + 1], afr[1], b1, b3);
        }
    }
}

// issue one chunk's A+B tiles with 256 threads: each thread 4x16B of A and 4x16B of B
__device__ __forceinline__ void issue_chunk(uint32_t Ab, uint32_t Bb,
                                            const __half* asrc, const __half* bsrc,
                                            uint32_t dstoff) {
#pragma unroll
    for (int s = 0; s < 4; s++) {
        CP16(Ab + swz(dstoff + 16 * s), asrc + 8 * s);
        CP16(Bb + swz(dstoff + 16 * s), bsrc + 8 * s);
    }
}

// =============================== pre: counters + fp16 converts ===============================
#define NX8  (NTOK * DDIM / 8)            // 262144
#define NW18 (NEXP * H2 * DDIM / 8)       // 1048576
#define NW28 (NEXP * DDIM * HDIM / 8)     // 524288
#define NPRE (NX8 + NW18 + NW28)
__global__ __launch_bounds__(256) void k_pre(const float* __restrict__ x,
                                             const float* __restrict__ w1,
                                             const float* __restrict__ w2) {
    int idx = blockIdx.x * blockDim.x + threadIdx.x;
    if (idx < NEXP) g_cnt[idx] = 0;
    if (idx < NX8) {
        ((uint4*)g_xh)[idx] = pack8(x + idx * 8);
    } else if (idx < NX8 + NW18) {
        int i2 = idx - NX8;
        int o  = i2 * 8;
        int orow = o >> 9;
        int k    = o & 511;
        int e = orow >> 11;
        int r = orow & 2047;
        const float* src = w1 + ((size_t)(e << 11) + ((r & 1) << 10) + (r >> 1)) * DDIM + k;
        ((uint4*)g_w1h)[i2] = pack8(src);
    } else if (idx < NPRE) {
        int i3 = idx - NX8 - NW18;
        ((uint4*)g_w2h)[i3] = pack8(w2 + i3 * 8);
    }
}

// =============================== router (fp32 exact) ===============================
__global__ __launch_bounds__(256) void k_router(const float* __restrict__ x,
                                                const float* __restrict__ rw,
                                                const float* __restrict__ rb) {
    int tok  = blockIdx.x * 8 + (threadIdx.x >> 5);
    int lane = threadIdx.x & 31;
    if (tok >= NTOK) return;
    const float* xr = x + (size_t)tok * DDIM;
    float acc[NEXP];
#pragma unroll
    for (int e = 0; e < NEXP; e++) acc[e] = 0.f;
    for (int i = lane; i < DDIM; i += 32) {
        float xv = xr[i];
#pragma unroll
        for (int e = 0; e < NEXP; e++) acc[e] += xv * rw[e * DDIM + i];
    }
#pragma unroll
    for (int e = 0; e < NEXP; e++) {
#pragma unroll
        for (int o = 16; o > 0; o >>= 1)
            acc[e] += __shfl_xor_sync(0xffffffffu, acc[e], o);
    }
    if (lane == 0) {
        float lg[NEXP];
#pragma unroll
        for (int e = 0; e < NEXP; e++) lg[e] = acc[e] + rb[e];
        int i0 = 0; float v0 = lg[0];
#pragma unroll
        for (int e = 1; e < NEXP; e++) if (lg[e] > v0) { v0 = lg[e]; i0 = e; }
        int i1 = -1; float v1 = -3.0e38f;
#pragma unroll
        for (int e = 0; e < NEXP; e++) if (e != i0 && lg[e] > v1) { v1 = lg[e]; i1 = e; }
        float t  = __expf(v1 - v0);
        float w0 = 1.f / (1.f + t);
        float w1_ = 1.f - w0;
        int s0 = atomicAdd(&g_cnt[i0], 1);
        g_tok[i0 * NTOK + s0] = tok;
        int s1 = atomicAdd(&g_cnt[i1], 1);
        g_tok[i1 * NTOK + s1] = tok;
        g_slot[tok] = make_int2(i0 * NTOK + s0, i1 * NTOK + s1);
        g_wp[tok]   = make_float2(w0, w1_);
    }
}

// =============================== fc1: mbarrier-pipelined fp16 mma + SwiGLU ===============================
// Block tile: 128 tokens x 128 interleaved cols (64 pairs). grid=(HDIM/64, NTOK/128, NEXP).
// 8 warps (4m x 2n), warp tile 32x64, 256 threads, 2 CTAs/SM.
__global__ __launch_bounds__(256, 2) void k_fc1(const float* __restrict__ b1) {
    int e   = blockIdx.z;
    int cnt = g_cnt[e];
    int m0  = blockIdx.y * 128;
    if (m0 >= cnt) return;
    int c0  = blockIdx.x * 64;   // pair base

    extern __shared__ char smem[];
    uint32_t sb    = smem_u32(smem);
    uint32_t tiles = (sb + 1023) & ~1023u;
    uint32_t hdr   = tiles + 3 * STAGE_BYTES;          // full[0..2] @ +0, empty[0..2] @ +24
    int* s_tok = (int*)(smem + (hdr - sb) + 64);

    int tid = threadIdx.x, wid = tid >> 5, lane = tid & 31;
    if (tid < 128) {
        int m = m0 + tid;
        s_tok[tid] = (m < cnt) ? g_tok[e * NTOK + m] : 0;
    }
    if (tid == 0) {
#pragma unroll
        for (int s = 0; s < 3; s++) {
            MBAR_INIT(hdr + 8 * s, 256);       // full: one cp-completion arrival per thread
            MBAR_INIT(hdr + 24 + 8 * s, 8);    // empty: one arrive per warp
        }
    }
    __syncthreads();

    uint32_t dstoff = (uint32_t)((tid >> 1) * 128 + (tid & 1) * 64);
    const __half* asrc = g_xh + (size_t)s_tok[tid >> 1] * DDIM + (tid & 1) * 32;
    const __half* bsrc = g_w1h + ((size_t)e * H2 + 2 * c0 + (tid >> 1)) * DDIM + (tid & 1) * 32;

    int wm = (wid >> 1) * 32;
    int wn = (wid & 1) * 64;
    float acc[2][8][4] = {};

    // prologue: stages 0,1 (first occupancy, no empty wait)
#pragma unroll
    for (int c = 0; c < 2; c++) {
        uint32_t Ab = tiles + c * STAGE_BYTES;
        issue_chunk(Ab, Ab + 16384, asrc + c * CH, bsrc + c * CH, dstoff);
        CP_ARRIVE(hdr + 8 * c);
    }

#pragma unroll
    for (int c = 0; c < NCH1; c++) {
        int cp = c + 2;
        if (cp < NCH1) {
            if (cp >= 3) mbar_wait(hdr + 24 + 8 * (cp % 3), ((cp - 3) / 3) & 1);
            uint32_t Ab = tiles + (cp % 3) * STAGE_BYTES;
            issue_chunk(Ab, Ab + 16384, asrc + cp * CH, bsrc + cp * CH, dstoff);
            CP_ARRIVE(hdr + 8 * (cp % 3));
        }
        mbar_wait(hdr + 8 * (c % 3), (c / 3) & 1);
        uint32_t Ab = tiles + (c % 3) * STAGE_BYTES;
        gemm64(Ab, Ab + 16384, wm, wn, lane, acc);
        if (lane == 0) MBAR_ARRIVE(hdr + 24 + 8 * (c % 3));
    }

    // epilogue: acc col pairs (even,odd) = (h1,h2); write fp16 activations
    const float* bb = b1 + (size_t)e * H2;
#pragma unroll
    for (int mt = 0; mt < 2; mt++) {
        int r_lo = m0 + wm + mt * 16 + (lane >> 2);
#pragma unroll
        for (int nt = 0; nt < 8; nt++) {
            int p = (wn >> 1) + nt * 4 + (lane & 3);
            int hcol = c0 + p;
            float bh1 = bb[hcol];
            float bh2 = bb[HDIM + hcol];
            if (r_lo < cnt) {
                float h1 = acc[mt][nt][0] + bh1;
                float h2 = acc[mt][nt][1] + bh2;
                g_act[((size_t)e * NTOK + r_lo) * HDIM + hcol] =
                    __float2half_rn((h1 / (1.f + __expf(-h1))) * h2);
            }
            int r_hi = r_lo + 8;
            if (r_hi < cnt) {
                float h1 = acc[mt][nt][2] + bh1;
                float h2 = acc[mt][nt][3] + bh2;
                g_act[((size_t)e * NTOK + r_hi) * HDIM + hcol] =
                    __float2half_rn((h1 / (1.f + __expf(-h1))) * h2);
            }
        }
    }
}

// =============================== fc2: mbarrier-pipelined fp16 mma, slot output ===============================
// Block tile: 128 tokens x 128 d-outputs. grid=(DDIM/128, NTOK/128, NEXP).
__global__ __launch_bounds__(256, 2) void k_fc2(const float* __restrict__ b2) {
    int e   = blockIdx.z;
    int cnt = g_cnt[e];
    int m0  = blockIdx.y * 128;
    if (m0 >= cnt) return;
    int n0  = blockIdx.x * 128;

    extern __shared__ char smem[];
    uint32_t sb    = smem_u32(smem);
    uint32_t tiles = (sb + 1023) & ~1023u;
    uint32_t hdr   = tiles + 3 * STAGE_BYTES;

    int tid = threadIdx.x, wid = tid >> 5, lane = tid & 31;
    if (tid == 0) {
#pragma unroll
        for (int s = 0; s < 3; s++) {
            MBAR_INIT(hdr + 8 * s, 256);
            MBAR_INIT(hdr + 24 + 8 * s, 8);
        }
    }
    __syncthreads();

    uint32_t dstoff = (uint32_t)((tid >> 1) * 128 + (tid & 1) * 64);
    const __half* asrc = g_act + ((size_t)e * NTOK + m0 + (tid >> 1)) * HDIM + (tid & 1) * 32;
    const __half* bsrc = g_w2h + ((size_t)e * DDIM + n0 + (tid >> 1)) * HDIM + (tid & 1) * 32;

    int wm = (wid >> 1) * 32;
    int wn = (wid & 1) * 64;
    float acc[2][8][4] = {};

#pragma unroll
    for (int c = 0; c < 2; c++) {
        uint32_t Ab = tiles + c * STAGE_BYTES;
        issue_chunk(Ab, Ab + 16384, asrc + c * CH, bsrc + c * CH, dstoff);
        CP_ARRIVE(hdr + 8 * c);
    }

#pragma unroll
    for (int c = 0; c < NCH2; c++) {
        int cp = c + 2;
        if (cp < NCH2) {
            if (cp >= 3) mbar_wait(hdr + 24 + 8 * (cp % 3), ((cp - 3) / 3) & 1);
            uint32_t Ab = tiles + (cp % 3) * STAGE_BYTES;
            issue_chunk(Ab, Ab + 16384, asrc + cp * CH, bsrc + cp * CH, dstoff);
            CP_ARRIVE(hdr + 8 * (cp % 3));
        }
        mbar_wait(hdr + 8 * (c % 3), (c / 3) & 1);
        uint32_t Ab = tiles + (c % 3) * STAGE_BYTES;
        gemm64(Ab, Ab + 16384, wm, wn, lane, acc);
        if (lane == 0) MBAR_ARRIVE(hdr + 24 + 8 * (c % 3));
    }

    // epilogue: y + bias -> g_y[slot] (plain float2 stores, fully parallel)
    const float* bb = b2 + (size_t)e * DDIM;
    float* ybase = g_y + ((size_t)e * NTOK + m0) * DDIM;
#pragma unroll
    for (int mt = 0; mt < 2; mt++) {
        int r_lo = wm + mt * 16 + (lane >> 2);
#pragma unroll
        for (int nt = 0; nt < 8; nt++) {
            int n_e = n0 + wn + nt * 8 + 2 * (lane & 3);
            float be = bb[n_e];
            float bo = bb[n_e + 1];
            if (m0 + r_lo < cnt)
                *(float2*)(ybase + (size_t)r_lo * DDIM + n_e) =
                    make_float2(acc[mt][nt][0] + be, acc[mt][nt][1] + bo);
            int r_hi = r_lo + 8;
            if (m0 + r_hi < cnt)
                *(float2*)(ybase + (size_t)r_hi * DDIM + n_e) =
                    make_float2(acc[mt][nt][2] + be, acc[mt][nt][3] + bo);
        }
    }
}

// =============================== combine: out = w0*y[slot0] + w1*y[slot1] ===============================
__global__ __launch_bounds__(256) void k_comb(float* __restrict__ out) {
    int tok  = blockIdx.x * 8 + (threadIdx.x >> 5);
    int lane = threadIdx.x & 31;
    int2   sl = g_slot[tok];
    float2 w  = g_wp[tok];
    const float* y0 = g_y + (size_t)sl.x * DDIM;
    const float* y1 = g_y + (size_t)sl.y * DDIM;
    float* op = out + (size_t)tok * DDIM;
#pragma unroll
    for (int i = 0; i < 4; i++) {
        int j = (i * 32 + lane) * 4;
        float4 a = *(const float4*)(y0 + j);
        float4 b = *(const float4*)(y1 + j);
        float4 r;
        r.x = w.x * a.x + w.y * b.x;
        r.y = w.x * a.y + w.y * b.y;
        r.z = w.x * a.z + w.y * b.z;
        r.w = w.x * a.w + w.y * b.w;
        *(float4*)(op + j) = r;
    }
}

// =============================== launch ===============================
extern "C" void kernel_launch(void* const* d_in, const int* in_sizes, int n_in,
                              void* d_out, int out_size) {
    const float* x   = (const float*)d_in[0];
    const float* rw  = (const float*)d_in[1];
    const float* rb  = (const float*)d_in[2];
    const float* f1w = (const float*)d_in[3];
    const float* f1b = (const float*)d_in[4];
    const float* f2w = (const float*)d_in[5];
    const float* f2b = (const float*)d_in[6];
    float* out = (float*)d_out;

    cudaFuncSetAttribute(k_fc1, cudaFuncAttributeMaxDynamicSharedMemorySize, SMEM_DYN);
    cudaFuncSetAttribute(k_fc2, cudaFuncAttributeMaxDynamicSharedMemorySize, SMEM_DYN);

    k_pre<<<(NPRE + 255) / 256, 256>>>(x, f1w, f2w);
    k_router<<<NTOK / 8, 256>>>(x, rw, rb);
    k_fc1<<<dim3(HDIM / 64, NTOK / 128, NEXP), 256, SMEM_DYN>>>(f1b);
    k_fc2<<<dim3(DDIM / 128, NTOK / 128, NEXP), 256, SMEM_DYN>>>(f2b);
    k_comb<<<NTOK / 8, 256>>>(out);
}